// round 9
// baseline (speedup 1.0000x reference)
#include <cuda_runtime.h>
#include <cstdint>

#define NB    24
#define NP1   25
#define NCOST (NB * NP1)      // 600 floats per batch
#define ND    256
#define INFX  1e9f
#define FULL  0xffffffffu
#define MAXB  2048

#define PH_SEARCH 0
#define PH_AUG    1
#define PH_DONE   2

// cost scratch: [B][24][25] fp32 (~4.9 MB), static device array (no allocs)
__device__ float g_cost[(size_t)MAXB * NCOST];

// packed fp32x2 FMA (sm_100+); doubles are 64-bit carriers for f32 pairs
__device__ __forceinline__ double ffma2(double a, double b, double c) {
    double r;
    asm("fma.rn.f32x2 %0, %1, %2, %3;" : "=d"(r) : "d"(a), "d"(b), "d"(c));
    return r;
}
__device__ __forceinline__ float pairsum(double a) {
    return __int_as_float(__double2loint(a)) + __int_as_float(__double2hiint(a));
}
// order-preserving float<->uint for unsigned min-reduction
__device__ __forceinline__ unsigned fenc(float x) {
    unsigned b = __float_as_uint(x);
    return b ^ (((unsigned)((int)b >> 31)) | 0x80000000u);
}
__device__ __forceinline__ float fdec(unsigned k) {
    unsigned m = ((unsigned)((int)(~k) >> 31)) | 0x80000000u;
    return __uint_as_float(k ^ m);
}

// 8-stream folded warp reduction (validated): lane L ends holding the sum of
// stream m(L) = bit4(L) | bit3(L)<<1 | bit2(L)<<2.
__device__ __forceinline__ float fold8(
    float q0, float q1, float q2, float q3,
    float q4, float q5, float q6, float q7, int lane)
{
    q0 += __shfl_xor_sync(FULL, q0, 16);
    q1 += __shfl_xor_sync(FULL, q1, 16);
    q2 += __shfl_xor_sync(FULL, q2, 16);
    q3 += __shfl_xor_sync(FULL, q3, 16);
    q4 += __shfl_xor_sync(FULL, q4, 16);
    q5 += __shfl_xor_sync(FULL, q5, 16);
    q6 += __shfl_xor_sync(FULL, q6, 16);
    q7 += __shfl_xor_sync(FULL, q7, 16);
    float t0 = (lane & 16) ? q1 : q0;
    float t1 = (lane & 16) ? q3 : q2;
    float t2 = (lane & 16) ? q5 : q4;
    float t3 = (lane & 16) ? q7 : q6;
    t0 += __shfl_xor_sync(FULL, t0, 8);
    t1 += __shfl_xor_sync(FULL, t1, 8);
    t2 += __shfl_xor_sync(FULL, t2, 8);
    t3 += __shfl_xor_sync(FULL, t3, 8);
    float u0 = (lane & 8) ? t1 : t0;
    float u1 = (lane & 8) ? t3 : t2;
    u0 += __shfl_xor_sync(FULL, u0, 4);
    u1 += __shfl_xor_sync(FULL, u1, 4);
    float v = (lane & 4) ? u1 : u0;
    v += __shfl_xor_sync(FULL, v, 2);
    v += __shfl_xor_sync(FULL, v, 1);
    return v;
}

// ============================================================================
// Kernel 1 (cost): CTA = one batch, 192 threads (6 warps). R6-validated math,
// now with software-pipelined j-blocks (prefetch t+1 while folding t).
// ============================================================================
__global__ __launch_bounds__(192) void costk(
    const float* __restrict__ slots,
    const float* __restrict__ prev,
    int B)
{
    __shared__ float ipn_s[NB];
    __shared__ float icn_s[NB];

    const int tid  = threadIdx.x;
    const int lane = tid & 31;
    const int w    = tid >> 5;           // 0..5
    const int b    = blockIdx.x;

    const float* sb = slots + (size_t)b * NB * ND;
    const float* pb = prev  + (size_t)b * NB * ND;

    // ---- prev i-block into registers + all inverse norms (one fold8) ----
    const int i0 = w * 4;
    double2 P[4][2];
    {
        float np[4], nc[4];
        #pragma unroll
        for (int r = 0; r < 4; r++) {
            const double2* pr = (const double2*)(pb + (i0 + r) * ND);
            P[r][0] = pr[lane];
            P[r][1] = pr[lane + 32];
            double an = 0.0;
            an = ffma2(P[r][0].x, P[r][0].x, an);
            an = ffma2(P[r][0].y, P[r][0].y, an);
            an = ffma2(P[r][1].x, P[r][1].x, an);
            an = ffma2(P[r][1].y, P[r][1].y, an);
            np[r] = pairsum(an);
            const double2* cr = (const double2*)(sb + (i0 + r) * ND);
            double2 c0 = cr[lane], c1 = cr[lane + 32];
            double cn = 0.0;
            cn = ffma2(c0.x, c0.x, cn);
            cn = ffma2(c0.y, c0.y, cn);
            cn = ffma2(c1.x, c1.x, cn);
            cn = ffma2(c1.y, c1.y, cn);
            nc[r] = pairsum(cn);
        }
        float v3 = fold8(np[0], np[1], np[2], np[3],
                         nc[0], nc[1], nc[2], nc[3], lane);
        float inv = 1.0f / fmaxf(sqrtf(v3), 1e-12f);
        if ((lane & 3) == 0) {
            int m = ((lane >> 4) & 1) | (((lane >> 3) & 1) << 1) | (((lane >> 2) & 1) << 2);
            if (m < 4) ipn_s[i0 + m]       = inv;
            else       icn_s[i0 + (m - 4)] = inv;
        }
    }
    __syncthreads();

    // ---- 6 j-blocks, software pipelined ----
    {
        const int m = ((lane >> 4) & 1) | (((lane >> 3) & 1) << 1) | (((lane >> 2) & 1) << 2);
        const int a = m >> 2;       // 0..1
        const int c = m & 3;        // 0..3
        const bool writer = ((lane & 3) == 0);
        float ipn1 = 0.f, ipn2 = 0.f;
        if (writer) {
            ipn1 = ipn_s[i0 + a];
            ipn2 = ipn_s[i0 + 2 + a];
        }
        float* gc = g_cost + (size_t)b * NCOST;

        double2 C0[4], C1[4];
        #pragma unroll
        for (int r = 0; r < 4; r++) {
            const double2* cr = (const double2*)(sb + r * ND);
            C0[r] = cr[lane];
            C1[r] = cr[lane + 32];
        }

        #pragma unroll
        for (int t = 0; t < 6; t++) {
            const int j0 = t * 4;
            // prefetch next j-block while this one computes/folds
            double2 N0[4], N1[4];
            if (t < 5) {
                #pragma unroll
                for (int r = 0; r < 4; r++) {
                    const double2* cr = (const double2*)(sb + (j0 + 4 + r) * ND);
                    N0[r] = cr[lane];
                    N1[r] = cr[lane + 32];
                }
            }
            // half 1: rows a=0,1
            {
                float s[8];
                #pragma unroll
                for (int aa = 0; aa < 2; aa++) {
                    #pragma unroll
                    for (int cc = 0; cc < 4; cc++) {
                        double acc = 0.0;
                        acc = ffma2(P[aa][0].x, C0[cc].x, acc);
                        acc = ffma2(P[aa][0].y, C0[cc].y, acc);
                        acc = ffma2(P[aa][1].x, C1[cc].x, acc);
                        acc = ffma2(P[aa][1].y, C1[cc].y, acc);
                        s[aa * 4 + cc] = pairsum(acc);
                    }
                }
                float v1 = fold8(s[0], s[1], s[2], s[3], s[4], s[5], s[6], s[7], lane);
                if (writer)
                    gc[(i0 + a) * NP1 + (j0 + c)] = 1.0f - v1 * ipn1 * icn_s[j0 + c];
            }
            // half 2: rows a=2,3
            {
                float s[8];
                #pragma unroll
                for (int aa = 0; aa < 2; aa++) {
                    #pragma unroll
                    for (int cc = 0; cc < 4; cc++) {
                        double acc = 0.0;
                        acc = ffma2(P[2 + aa][0].x, C0[cc].x, acc);
                        acc = ffma2(P[2 + aa][0].y, C0[cc].y, acc);
                        acc = ffma2(P[2 + aa][1].x, C1[cc].x, acc);
                        acc = ffma2(P[2 + aa][1].y, C1[cc].y, acc);
                        s[aa * 4 + cc] = pairsum(acc);
                    }
                }
                float v2 = fold8(s[0], s[1], s[2], s[3], s[4], s[5], s[6], s[7], lane);
                if (writer)
                    gc[(i0 + 2 + a) * NP1 + (j0 + c)] = 1.0f - v2 * ipn2 * icn_s[j0 + c];
            }
            if (t < 5) {
                #pragma unroll
                for (int r = 0; r < 4; r++) { C0[r] = N0[r]; C1[r] = N1[r]; }
            }
        }
    }
}

// ============================================================================
// JV state machine. lane j owns column j. up = u[p[j]] (potential of the row
// currently assigned to this column) — provably identical to indexing u by
// row: rows on the Dijkstra path are exactly {p[j] : used j} (incl. the
// entering row at the virtual column), so "row_used" == "used" per lane, and
// augmentation moves rows with their potentials (up follows p along hops).
// Arithmetic per step is byte-identical to the validated R2..R8 formulation.
// ============================================================================
struct JVS {
    const float* cw;
    float v, up, minv;
    int   p, way, j0, pj0;
    bool  used;
    unsigned matched;   // rows matched by column reduction
    int   i;            // current row
    int   phase;
};

__device__ __forceinline__ void jv_start_row(JVS& s, int lane) {
    while (s.i < NB && ((s.matched >> s.i) & 1u)) s.i++;
    if (s.i >= NB) { s.phase = PH_DONE; return; }
    if (lane == NB) { s.p = s.i; s.up = 0.0f; }  // entering row: never matched before => u=0
    s.minv = INFX; s.way = 0; s.used = false;
    s.j0 = NB; s.pj0 = s.i;
    s.phase = PH_SEARCH;
}

__device__ __forceinline__ void jv_init(JVS& s, const float* cw, int lane) {
    s.cw = cw;
    s.v = 0.0f; s.up = 0.0f; s.p = -1; s.i = 0;
    // column reduction: v[j] = min_i c[i][j]; greedy unique-argmin matching
    int rmin = 32 + lane;   // unique sentinel for lanes >= NB
    if (lane < NB) {
        float m = INFX;
        rmin = 0;
        #pragma unroll
        for (int r = 0; r < NB; r++) {
            float c = cw[r * NP1 + lane];
            if (c < m) { m = c; rmin = r; }   // first-index on ties
        }
        s.v = m;
    }
    unsigned grp = __match_any_sync(FULL, rmin);
    bool claim = (lane < NB) && (lane == __ffs(grp) - 1);  // lowest col wins row
    if (claim) s.p = rmin;
    s.matched = __reduce_or_sync(FULL, claim ? (1u << rmin) : 0u);
    jv_start_row(s, lane);
}

__device__ __forceinline__ void jv_advance(JVS& s, int lane, unsigned ENC_INF) {
    if (s.phase == PH_SEARCH) {
        s.used = s.used || (lane == s.j0);
        float u_i0 = __shfl_sync(FULL, s.up, s.j0);
        float crow = (lane < NB) ? s.cw[s.pj0 * NP1 + lane] : 0.0f;
        bool  act  = (lane < NB) && !s.used;
        if (act) {
            float cv = crow - u_i0 - s.v;     // reduced cost
            if (cv < s.minv) { s.minv = cv; s.way = s.j0; }
        }
        unsigned key  = act ? fenc(s.minv) : ENC_INF;
        unsigned kmin = __reduce_min_sync(FULL, key);
        int j1 = __ffs(__ballot_sync(FULL, key == kmin)) - 1;
        float delta = fdec(kmin);
        if (s.used) { s.v -= delta; s.up += delta; }
        else if (act) s.minv -= delta;
        s.j0  = j1;
        s.pj0 = __shfl_sync(FULL, s.p, j1);
        if (s.pj0 < 0) s.phase = PH_AUG;      // reached a free column
    } else if (s.phase == PH_AUG) {
        // one augment hop back toward the virtual column
        int jp = __shfl_sync(FULL, s.way, s.j0);
        int pv = __shfl_sync(FULL, s.p, jp);
        float uv = __shfl_sync(FULL, s.up, jp);
        if (lane == s.j0) { s.p = pv; s.up = uv; }
        s.j0 = jp;
        if (s.j0 == NB) { s.i++; jv_start_row(s, lane); }
    }
}

// ============================================================================
// Kernel 2: JV + gather, TWO batches per warp with STEP-LEVEL interleave.
// The two state machines advance alternately in one loop; their dependence
// chains are independent and overlap in the scheduler.
// ============================================================================
__global__ __launch_bounds__(128) void jvk(
    const float* __restrict__ slots,
    float* __restrict__ out,
    int B)
{
    __shared__ float cost_s[8][NCOST];
    __shared__ int   col_s[8][NB];

    const int lane = threadIdx.x & 31;
    const int w    = threadIdx.x >> 5;
    const int bA   = blockIdx.x * 8 + w * 2;
    const int bB   = bA + 1;
    const bool hasA = bA < B;
    const bool hasB = bB < B;
    if (!hasA) return;

    // ---- stage cost matrices (g_cost is L2-resident) ----
    {
        const float4* gA = (const float4*)(g_cost + (size_t)bA * NCOST);
        float4* cA = (float4*)cost_s[w * 2];
        #pragma unroll
        for (int t = lane; t < NCOST / 4; t += 32) cA[t] = gA[t];
        if (hasB) {
            const float4* gB = (const float4*)(g_cost + (size_t)bB * NCOST);
            float4* cB = (float4*)cost_s[w * 2 + 1];
            #pragma unroll
            for (int t = lane; t < NCOST / 4; t += 32) cB[t] = gB[t];
        }
    }
    __syncwarp();

    const unsigned ENC_INF = fenc(INFX);
    JVS A, Bst;
    jv_init(A, cost_s[w * 2], lane);
    if (hasB) jv_init(Bst, cost_s[w * 2 + 1], lane);
    else      Bst.phase = PH_DONE;

    while (A.phase != PH_DONE || Bst.phase != PH_DONE) {
        jv_advance(A, lane, ENC_INF);
        jv_advance(Bst, lane, ENC_INF);
    }

    if (lane < NB) {
        col_s[w * 2][A.p] = lane;           // col index of row p[j] is j
        if (hasB) col_s[w * 2 + 1][Bst.p] = lane;
    }
    __syncwarp();

    // ---- gather both batches ----
    #pragma unroll
    for (int q = 0; q < 2; q++) {
        if (q == 1 && !hasB) break;
        const int b = bA + q;
        const float* sb = slots + (size_t)b * NB * ND;
        float*       ob = out   + (size_t)b * NB * ND;
        const int*   cs = col_s[w * 2 + q];
        for (int rr = 0; rr < NB; rr++) {
            int src = cs[rr];
            const float4* s4 = (const float4*)(sb + src * ND);
            float4*       o4 = (float4*)(ob + rr * ND);
            o4[lane]      = s4[lane];
            o4[lane + 32] = s4[lane + 32];
        }
    }
}

extern "C" void kernel_launch(void* const* d_in, const int* in_sizes, int n_in,
                              void* d_out, int out_size) {
    const float* slots = (const float*)d_in[0];
    const float* prev  = (const float*)d_in[1];
    float* out = (float*)d_out;
    int B = in_sizes[0] / (NB * ND);
    if (B > MAXB) B = MAXB;

    costk<<<B, 192>>>(slots, prev, B);

    int grid2 = (B + 7) / 8;    // 8 batches per CTA (2 per warp)
    jvk<<<grid2, 128>>>(slots, out, B);
}

// round 10
// speedup vs baseline: 1.3549x; 1.3549x over previous
#include <cuda_runtime.h>
#include <cstdint>

#define NB    24
#define NP1   25
#define NCOST (NB * NP1)      // 600 floats per batch
#define ND    256
#define INFX  1e9f
#define FULL  0xffffffffu
#define MAXB  2048

// cost scratch: [B][24][25] fp32 (~4.9 MB), static device array (no allocs)
__device__ float g_cost[(size_t)MAXB * NCOST];

// packed fp32x2 FMA (sm_100+); doubles are 64-bit carriers for f32 pairs
__device__ __forceinline__ double ffma2(double a, double b, double c) {
    double r;
    asm("fma.rn.f32x2 %0, %1, %2, %3;" : "=d"(r) : "d"(a), "d"(b), "d"(c));
    return r;
}
__device__ __forceinline__ float pairsum(double a) {
    return __int_as_float(__double2loint(a)) + __int_as_float(__double2hiint(a));
}
// order-preserving float<->uint for unsigned min-reduction
__device__ __forceinline__ unsigned fenc(float x) {
    unsigned b = __float_as_uint(x);
    return b ^ (((unsigned)((int)b >> 31)) | 0x80000000u);
}
__device__ __forceinline__ float fdec(unsigned k) {
    unsigned m = ((unsigned)((int)(~k) >> 31)) | 0x80000000u;
    return __uint_as_float(k ^ m);
}

// 8-stream folded warp reduction (validated): lane L ends holding the sum of
// stream m(L) = bit4(L) | bit3(L)<<1 | bit2(L)<<2.
__device__ __forceinline__ float fold8(
    float q0, float q1, float q2, float q3,
    float q4, float q5, float q6, float q7, int lane)
{
    q0 += __shfl_xor_sync(FULL, q0, 16);
    q1 += __shfl_xor_sync(FULL, q1, 16);
    q2 += __shfl_xor_sync(FULL, q2, 16);
    q3 += __shfl_xor_sync(FULL, q3, 16);
    q4 += __shfl_xor_sync(FULL, q4, 16);
    q5 += __shfl_xor_sync(FULL, q5, 16);
    q6 += __shfl_xor_sync(FULL, q6, 16);
    q7 += __shfl_xor_sync(FULL, q7, 16);
    float t0 = (lane & 16) ? q1 : q0;
    float t1 = (lane & 16) ? q3 : q2;
    float t2 = (lane & 16) ? q5 : q4;
    float t3 = (lane & 16) ? q7 : q6;
    t0 += __shfl_xor_sync(FULL, t0, 8);
    t1 += __shfl_xor_sync(FULL, t1, 8);
    t2 += __shfl_xor_sync(FULL, t2, 8);
    t3 += __shfl_xor_sync(FULL, t3, 8);
    float u0 = (lane & 8) ? t1 : t0;
    float u1 = (lane & 8) ? t3 : t2;
    u0 += __shfl_xor_sync(FULL, u0, 4);
    u1 += __shfl_xor_sync(FULL, u1, 4);
    float v = (lane & 4) ? u1 : u0;
    v += __shfl_xor_sync(FULL, v, 2);
    v += __shfl_xor_sync(FULL, v, 1);
    return v;
}

// ============================================================================
// Kernel 1 (cost): CTA = one batch, 192 threads (6 warps). Validated R6.
// ============================================================================
__global__ __launch_bounds__(192) void costk(
    const float* __restrict__ slots,
    const float* __restrict__ prev,
    int B)
{
    __shared__ float ipn_s[NB];
    __shared__ float icn_s[NB];

    const int tid  = threadIdx.x;
    const int lane = tid & 31;
    const int w    = tid >> 5;           // 0..5
    const int b    = blockIdx.x;

    const float* sb = slots + (size_t)b * NB * ND;
    const float* pb = prev  + (size_t)b * NB * ND;

    // ---- prev i-block into registers + all inverse norms (one fold8) ----
    const int i0 = w * 4;
    double2 P[4][2];
    {
        float np[4], nc[4];
        #pragma unroll
        for (int r = 0; r < 4; r++) {
            const double2* pr = (const double2*)(pb + (i0 + r) * ND);
            P[r][0] = pr[lane];
            P[r][1] = pr[lane + 32];
            double an = 0.0;
            an = ffma2(P[r][0].x, P[r][0].x, an);
            an = ffma2(P[r][0].y, P[r][0].y, an);
            an = ffma2(P[r][1].x, P[r][1].x, an);
            an = ffma2(P[r][1].y, P[r][1].y, an);
            np[r] = pairsum(an);
            const double2* cr = (const double2*)(sb + (i0 + r) * ND);
            double2 c0 = cr[lane], c1 = cr[lane + 32];
            double cn = 0.0;
            cn = ffma2(c0.x, c0.x, cn);
            cn = ffma2(c0.y, c0.y, cn);
            cn = ffma2(c1.x, c1.x, cn);
            cn = ffma2(c1.y, c1.y, cn);
            nc[r] = pairsum(cn);
        }
        float v3 = fold8(np[0], np[1], np[2], np[3],
                         nc[0], nc[1], nc[2], nc[3], lane);
        float inv = 1.0f / fmaxf(sqrtf(v3), 1e-12f);
        if ((lane & 3) == 0) {
            int m = ((lane >> 4) & 1) | (((lane >> 3) & 1) << 1) | (((lane >> 2) & 1) << 2);
            if (m < 4) ipn_s[i0 + m]       = inv;
            else       icn_s[i0 + (m - 4)] = inv;
        }
    }
    __syncthreads();

    // ---- 6 j-blocks of 4 cur rows (global/L1), two 8-dot halves each ----
    {
        const int m = ((lane >> 4) & 1) | (((lane >> 3) & 1) << 1) | (((lane >> 2) & 1) << 2);
        const int a = m >> 2;       // 0..1
        const int c = m & 3;        // 0..3
        const bool writer = ((lane & 3) == 0);
        float ipn1 = 0.f, ipn2 = 0.f;
        if (writer) {
            ipn1 = ipn_s[i0 + a];
            ipn2 = ipn_s[i0 + 2 + a];
        }
        float* gc = g_cost + (size_t)b * NCOST;

        #pragma unroll
        for (int t = 0; t < 6; t++) {
            const int j0 = t * 4;
            double2 C0[4], C1[4];
            #pragma unroll
            for (int r = 0; r < 4; r++) {
                const double2* cr = (const double2*)(sb + (j0 + r) * ND);
                C0[r] = cr[lane];
                C1[r] = cr[lane + 32];
            }
            {
                float s[8];
                #pragma unroll
                for (int aa = 0; aa < 2; aa++) {
                    #pragma unroll
                    for (int cc = 0; cc < 4; cc++) {
                        double acc = 0.0;
                        acc = ffma2(P[aa][0].x, C0[cc].x, acc);
                        acc = ffma2(P[aa][0].y, C0[cc].y, acc);
                        acc = ffma2(P[aa][1].x, C1[cc].x, acc);
                        acc = ffma2(P[aa][1].y, C1[cc].y, acc);
                        s[aa * 4 + cc] = pairsum(acc);
                    }
                }
                float v1 = fold8(s[0], s[1], s[2], s[3], s[4], s[5], s[6], s[7], lane);
                if (writer)
                    gc[(i0 + a) * NP1 + (j0 + c)] = 1.0f - v1 * ipn1 * icn_s[j0 + c];
            }
            {
                float s[8];
                #pragma unroll
                for (int aa = 0; aa < 2; aa++) {
                    #pragma unroll
                    for (int cc = 0; cc < 4; cc++) {
                        double acc = 0.0;
                        acc = ffma2(P[2 + aa][0].x, C0[cc].x, acc);
                        acc = ffma2(P[2 + aa][0].y, C0[cc].y, acc);
                        acc = ffma2(P[2 + aa][1].x, C1[cc].x, acc);
                        acc = ffma2(P[2 + aa][1].y, C1[cc].y, acc);
                        s[aa * 4 + cc] = pairsum(acc);
                    }
                }
                float v2 = fold8(s[0], s[1], s[2], s[3], s[4], s[5], s[6], s[7], lane);
                if (writer)
                    gc[(i0 + 2 + a) * NP1 + (j0 + c)] = 1.0f - v2 * ipn2 * icn_s[j0 + c];
            }
        }
    }
}

// ============================================================================
// Kernel 2: JV Hungarian + gather. One warp per batch, 4 warps/CTA.
// R8-validated structure; NEW: augmenting row reduction after the column
// reduction. u is held BY ROW in lane registers (lane r = u[row r], exactly
// as in R8); row reduction initializes u[i] = min_j (c[i][j] - v[j]) for free
// rows and greedily matches rows whose argmin column is free. Duals remain
// feasible with zero reduced cost on matched arcs, so the validated
// shortest-augmenting-path search (byte-identical below) stays exact.
// ============================================================================
__global__ __launch_bounds__(128) void jvk(
    const float* __restrict__ slots,
    float* __restrict__ out,
    int B)
{
    __shared__ float cost_s[4][NCOST];
    __shared__ int   col_s[4][NB];

    const int lane = threadIdx.x & 31;
    const int w    = threadIdx.x >> 5;
    const int b    = blockIdx.x * 4 + w;
    if (b >= B) return;

    // ---- stage this batch's cost matrix into smem (600 floats) ----
    {
        const float4* gc4 = (const float4*)(g_cost + (size_t)b * NCOST);
        float4* cs4 = (float4*)cost_s[w];
        #pragma unroll
        for (int t = lane; t < NCOST / 4; t += 32)
            cs4[t] = gc4[t];
    }
    __syncwarp();

    const float* cw = cost_s[w];
    const unsigned ENC_INF = fenc(INFX);

    float u = 0.0f, v = 0.0f;
    int   p = -1;
    unsigned rowmask = 0;       // bit r set => row r matched

    // ---- column reduction: v[j] = min_i c[i][j]; greedy argmin matching ----
    {
        int rmin = 32 + lane;   // unique sentinel for lanes >= NB
        if (lane < NB) {
            float m = INFX;
            rmin = 0;
            #pragma unroll
            for (int i = 0; i < NB; i++) {
                float c = cw[i * NP1 + lane];
                if (c < m) { m = c; rmin = i; }   // first-index on ties
            }
            v = m;
        }
        unsigned grp = __match_any_sync(FULL, rmin);
        bool claim = (lane < NB) && (lane == __ffs(grp) - 1);  // lowest col wins row
        if (claim) p = rmin;
        rowmask = __reduce_or_sync(FULL, claim ? (1u << rmin) : 0u);
    }

    // ---- NEW: augmenting row reduction over still-free rows ----
    // u[i] = min_j (c[i][j] - v[j]); if the argmin column is free, match it.
    // Feasibility: reduced costs of row i become >= 0 with equality at j1;
    // v untouched, so all other rows unaffected.
    {
        unsigned freerows = ~rowmask & ((1u << NB) - 1u);
        while (freerows) {
            int i = __ffs(freerows) - 1;
            freerows &= freerows - 1;
            float rc = (lane < NB) ? cw[i * NP1 + lane] - v : INFX;
            unsigned key  = (lane < NB) ? fenc(rc) : ENC_INF;
            unsigned kmin = __reduce_min_sync(FULL, key);
            int j1 = __ffs(__ballot_sync(FULL, key == kmin)) - 1;
            float ui = fdec(kmin);
            if (lane == i) u = ui;                 // row potential (by-row in lanes)
            int pj1 = __shfl_sync(FULL, p, j1);
            if (pj1 < 0) {                         // column free -> match (i, j1)
                if (lane == j1) p = i;
                rowmask |= 1u << i;
            }
        }
    }

    // ---- augmenting-path searches for remaining free rows (validated) ----
    for (int i = 0; i < NB; i++) {
        if ((rowmask >> i) & 1u) continue;     // row already matched

        if (lane == NB) p = i;        // virtual start column holds new row
        float minv = INFX;
        int   way  = 0;
        bool  used = false;
        bool  row_used = false;
        int   j0  = NB;
        int   pj0 = i;

        while (true) {
            used     = used     || (lane == j0);
            row_used = row_used || (lane == pj0);
            float u_i0 = __shfl_sync(FULL, u, pj0);
            float crow = (lane < NB) ? cw[pj0 * NP1 + lane] : 0.0f;
            bool  act  = (lane < NB) && !used;
            if (act) {
                float cv = crow - u_i0 - v;       // reduced cost
                if (cv < minv) { minv = cv; way = j0; }
            }
            unsigned key  = act ? fenc(minv) : ENC_INF;
            unsigned kmin = __reduce_min_sync(FULL, key);
            int j1 = __ffs(__ballot_sync(FULL, key == kmin)) - 1;
            float delta = fdec(kmin);
            if (used)     v    -= delta;
            if (row_used) u    += delta;
            if (act)      minv -= delta;
            j0  = j1;
            pj0 = __shfl_sync(FULL, p, j0);
            if (pj0 < 0) break;      // reached a free column
        }
        // augment along parent pointers back to virtual column
        while (j0 != NB) {
            int jp = __shfl_sync(FULL, way, j0);
            int pv = __shfl_sync(FULL, p, jp);
            if (lane == j0) p = pv;
            j0 = jp;
        }
    }
    if (lane < NB) col_s[w][p] = lane;   // col index of row p[j] is j
    __syncwarp();

    // ---- gather: out[row][:] = slots[col[row]][:] ----
    const float* sb = slots + (size_t)b * NB * ND;
    float*       ob = out   + (size_t)b * NB * ND;
    for (int rr = 0; rr < NB; rr++) {
        int src = col_s[w][rr];
        const float4* s4 = (const float4*)(sb + src * ND);
        float4*       o4 = (float4*)(ob + rr * ND);
        o4[lane]      = s4[lane];
        o4[lane + 32] = s4[lane + 32];
    }
}

extern "C" void kernel_launch(void* const* d_in, const int* in_sizes, int n_in,
                              void* d_out, int out_size) {
    const float* slots = (const float*)d_in[0];
    const float* prev  = (const float*)d_in[1];
    float* out = (float*)d_out;
    int B = in_sizes[0] / (NB * ND);
    if (B > MAXB) B = MAXB;

    costk<<<B, 192>>>(slots, prev, B);

    int grid2 = (B + 3) / 4;
    jvk<<<grid2, 128>>>(slots, out, B);
}